// round 4
// baseline (speedup 1.0000x reference)
#include <cuda_runtime.h>
#include <math.h>
#include <stdint.h>

// ---------------------------------------------------------------------------
// PhysicsGraphFusion: B=1024 graphs, N=7 nodes, D=1024 dim.
// Round 3: 3xTF32 mma.sync GEMM with global prefetch double-buffering,
// interleaved (hi,lo) float2 smem (LDS.64, conflict-free), and a merged
// 5-way projection GEMM (N=5120).
// ---------------------------------------------------------------------------

#define BB   1024
#define NN   7
#define DD   1024
#define MM   (BB*NN)          // 7168
#define NP   (5*DD)           // 5120 packed projection width

static const size_t OFF_FUSED = 0;
static const size_t OFF_UPD   = (size_t)BB*DD;
static const size_t OFF_IMP   = OFF_UPD + (size_t)MM*DD;
static const size_t OFF_ATTN  = OFF_IMP + (size_t)MM;
static const size_t OFF_PHYS  = OFF_ATTN + (size_t)BB*NN*NN;
static const size_t OFF_ALIGN = OFF_PHYS + 1;

// ---------------- device scratch (static; no runtime allocation) -----------
__device__ float g_qkv [ (size_t)MM*NP ];      // q|k|v|la|rb packed, stride 5120
__device__ float g_wpack[ (size_t)DD*NP ];
__device__ float g_bpack[ NP ];
__device__ float g_cc  [ (size_t)BB*DD ];
__device__ float g_msg [ (size_t)MM*DD ];
__device__ float g_cat [ (size_t)MM*2*DD ];
__device__ float g_hid [ (size_t)MM*DD ];
__device__ float g_implog[ MM ];
__device__ float g_phys_part [ BB ];
__device__ float g_align_part[ BB ];

__constant__ float c_adj[49] = {
    1,1,0,0,1,1,1,
    1,1,1,1,1,1,1,
    0,1,1,0,1,0,1,
    0,1,0,1,1,1,1,
    1,1,1,1,1,1,1,
    1,1,0,1,1,1,1,
    1,1,1,1,1,1,1 };

__device__ __forceinline__ float geluf(float x) {
    return 0.5f * x * (1.0f + erff(x * 0.70710678118654752440f));
}

__device__ __forceinline__ float tf32_rna(float x) {
    float r;
    asm("cvt.rna.tf32.f32 %0, %1;" : "=f"(r) : "f"(x));
    return r;
}

__device__ __forceinline__ void mma_tf32(float* c,
    uint32_t a0, uint32_t a1, uint32_t a2, uint32_t a3,
    uint32_t b0, uint32_t b1)
{
    asm volatile(
        "mma.sync.aligned.m16n8k8.row.col.f32.tf32.tf32.f32 "
        "{%0,%1,%2,%3}, {%4,%5,%6,%7}, {%8,%9}, {%0,%1,%2,%3};\n"
        : "+f"(c[0]), "+f"(c[1]), "+f"(c[2]), "+f"(c[3])
        : "r"(a0), "r"(a1), "r"(a2), "r"(a3), "r"(b0), "r"(b1));
}

// ---------------------------------------------------------------------------
// Tensor-core GEMM: C[M,Nc] = epi(A[M,K] @ W[K,Nc] + bias), 3xTF32.
// BM=BN=128, BK=32, 256 threads (8 warps, 4x2), warp tile 32x64.
// smem: float2 (hi,lo) interleaved. A: [128][AS2], B: [32][BS2].
// AS2*2 = 72 words ≡ 8 (mod 32); BS2*2 = 264 words ≡ 8 (mod 32):
// fragment LDS.64 patterns are bank-conflict-free in both half-warp phases.
// ---------------------------------------------------------------------------
#define AS2 36
#define BS2 132
#define SMEM_GEMM_BYTES ((128*AS2 + 32*BS2) * 8)   // 70,656 B

__global__ __launch_bounds__(256)
void gemm_tc_kernel(int M, int Nc, int K,
                    const float* __restrict__ A, int lda,
                    const float* __restrict__ W,
                    const float* __restrict__ bias,
                    const float* __restrict__ resid,
                    float* __restrict__ C,
                    int applyGelu)
{
    extern __shared__ float2 sm2[];
    float2* As2 = sm2;                 // [128][AS2]
    float2* Bs2 = sm2 + 128 * AS2;     // [32][BS2]

    const int tid  = threadIdx.x;
    const int lane = tid & 31;
    const int wid  = tid >> 5;
    const int wm   = wid & 3;
    const int wn   = wid >> 2;
    const int gid  = lane >> 2;
    const int tig  = lane & 3;

    const int brow = blockIdx.y;
    const int bcol = blockIdx.x;

    const float* Aptr = A + (size_t)(brow * 128) * lda;
    const float* Wptr = W + (size_t)bcol * 128;

    // per-thread loader coordinates (4 float4 each for A and B per chunk)
    int ar[4], ac4[4], br[4], bc4[4];
    #pragma unroll
    for (int it = 0; it < 4; it++) {
        int idx = it * 256 + tid;
        ar[it]  = idx >> 3;  ac4[it] = (idx & 7) * 4;
        br[it]  = idx >> 5;  bc4[it] = (idx & 31) * 4;
    }

    float acc[2][8][4];
    #pragma unroll
    for (int mi = 0; mi < 2; mi++)
        #pragma unroll
        for (int ni = 0; ni < 8; ni++)
            #pragma unroll
            for (int r = 0; r < 4; r++) acc[mi][ni][r] = 0.0f;

    float4 pa[4], pb[4];
    #pragma unroll
    for (int it = 0; it < 4; it++) {
        pa[it] = *(const float4*)(Aptr + (size_t)ar[it] * lda + ac4[it]);
        pb[it] = *(const float4*)(Wptr + (size_t)br[it] * Nc + bc4[it]);
    }

    for (int k0 = 0; k0 < K; k0 += 32) {
        // ---- store prefetched chunk to smem with hi/lo split ----
        #pragma unroll
        for (int it = 0; it < 4; it++) {
            float h0 = tf32_rna(pa[it].x), l0 = tf32_rna(pa[it].x - h0);
            float h1 = tf32_rna(pa[it].y), l1 = tf32_rna(pa[it].y - h1);
            float h2 = tf32_rna(pa[it].z), l2 = tf32_rna(pa[it].z - h2);
            float h3 = tf32_rna(pa[it].w), l3 = tf32_rna(pa[it].w - h3);
            float4* dA = (float4*)&As2[ar[it] * AS2 + ac4[it]];
            dA[0] = make_float4(h0, l0, h1, l1);
            dA[1] = make_float4(h2, l2, h3, l3);

            h0 = tf32_rna(pb[it].x); l0 = tf32_rna(pb[it].x - h0);
            h1 = tf32_rna(pb[it].y); l1 = tf32_rna(pb[it].y - h1);
            h2 = tf32_rna(pb[it].z); l2 = tf32_rna(pb[it].z - h2);
            h3 = tf32_rna(pb[it].w); l3 = tf32_rna(pb[it].w - h3);
            float4* dB = (float4*)&Bs2[br[it] * BS2 + bc4[it]];
            dB[0] = make_float4(h0, l0, h1, l1);
            dB[1] = make_float4(h2, l2, h3, l3);
        }
        __syncthreads();

        // ---- prefetch next chunk (overlaps with compute below) ----
        if (k0 + 32 < K) {
            #pragma unroll
            for (int it = 0; it < 4; it++) {
                pa[it] = *(const float4*)(Aptr + (size_t)ar[it] * lda + (k0 + 32) + ac4[it]);
                pb[it] = *(const float4*)(Wptr + (size_t)(k0 + 32 + br[it]) * Nc + bc4[it]);
            }
        }

        // ---- compute ----
        #pragma unroll
        for (int kk = 0; kk < 4; kk++) {
            float2 af[2][4];
            #pragma unroll
            for (int mi = 0; mi < 2; mi++) {
                int r0 = (wm * 32 + mi * 16 + gid) * AS2 + kk * 8 + tig;
                af[mi][0] = As2[r0];
                af[mi][1] = As2[r0 + 8 * AS2];
                af[mi][2] = As2[r0 + 4];
                af[mi][3] = As2[r0 + 8 * AS2 + 4];
            }
            #pragma unroll
            for (int ni = 0; ni < 8; ni++) {
                int bi = (kk * 8 + tig) * BS2 + wn * 64 + ni * 8 + gid;
                float2 b0 = Bs2[bi];
                float2 b1 = Bs2[bi + 4 * BS2];
                uint32_t bh0 = __float_as_uint(b0.x), bl0 = __float_as_uint(b0.y);
                uint32_t bh1 = __float_as_uint(b1.x), bl1 = __float_as_uint(b1.y);
                #pragma unroll
                for (int mi = 0; mi < 2; mi++) {
                    uint32_t ah0 = __float_as_uint(af[mi][0].x);
                    uint32_t ah1 = __float_as_uint(af[mi][1].x);
                    uint32_t ah2 = __float_as_uint(af[mi][2].x);
                    uint32_t ah3 = __float_as_uint(af[mi][3].x);
                    mma_tf32(acc[mi][ni], ah0, ah1, ah2, ah3, bh0, bh1);
                    mma_tf32(acc[mi][ni], ah0, ah1, ah2, ah3, bl0, bl1);
                    mma_tf32(acc[mi][ni],
                             __float_as_uint(af[mi][0].y), __float_as_uint(af[mi][1].y),
                             __float_as_uint(af[mi][2].y), __float_as_uint(af[mi][3].y),
                             bh0, bh1);
                }
            }
        }
        __syncthreads();
    }

    // ---- epilogue ----
    #pragma unroll
    for (int mi = 0; mi < 2; mi++) {
        #pragma unroll
        for (int ni = 0; ni < 8; ni++) {
            int row0 = brow * 128 + wm * 32 + mi * 16 + gid;
            int col0 = bcol * 128 + wn * 64 + ni * 8 + tig * 2;
            #pragma unroll
            for (int half = 0; half < 2; half++) {
                int row = row0 + half * 8;
                size_t base = (size_t)row * Nc + col0;
                float v0 = acc[mi][ni][half * 2 + 0];
                float v1 = acc[mi][ni][half * 2 + 1];
                if (bias) { v0 += bias[col0]; v1 += bias[col0 + 1]; }
                if (applyGelu) { v0 = geluf(v0); v1 = geluf(v1); }
                if (resid) { v0 += resid[base]; v1 += resid[base + 1]; }
                C[base]     = v0;
                C[base + 1] = v1;
            }
        }
    }
}

// ---------------------------------------------------------------------------
// Weight/bias packing for the merged projection GEMM:
// g_wpack[K=1024][5120] = [Wq | Wk | Wv | We1_a | We1_b] column blocks
// ---------------------------------------------------------------------------
__global__ void pack_w_kernel(const float* __restrict__ Wq,
                              const float* __restrict__ Wk,
                              const float* __restrict__ Wv,
                              const float* __restrict__ We1)
{
    size_t i = (size_t)blockIdx.x * blockDim.x + threadIdx.x;
    if (i >= (size_t)DD * NP) return;
    int r   = (int)(i / NP);
    int c   = (int)(i % NP);
    int seg = c >> 10;
    int cc  = c & 1023;
    const float* src;
    if      (seg == 0) src = Wq;
    else if (seg == 1) src = Wk;
    else if (seg == 2) src = Wv;
    else if (seg == 3) src = We1;
    else               src = We1 + (size_t)DD * DD;
    g_wpack[i] = src[(size_t)r * DD + cc];
}

__global__ void pack_b_kernel(const float* __restrict__ bq,
                              const float* __restrict__ bk,
                              const float* __restrict__ bv)
{
    int c = blockIdx.x * blockDim.x + threadIdx.x;
    if (c >= NP) return;
    int seg = c >> 10, cc = c & 1023;
    float v = 0.0f;
    if      (seg == 0) v = bq[cc];
    else if (seg == 1) v = bk[cc];
    else if (seg == 2) v = bv[cc];
    g_bpack[c] = v;
}

// ---------------------------------------------------------------------------
// Per-batch attention: edge-MLP logits + q.k logits + mask + softmax + messages
// Reads q/k/v/la/rb from packed g_qkv (row stride NP).
// ---------------------------------------------------------------------------
__global__ __launch_bounds__(256)
void attn_kernel(const float* __restrict__ be1,
                 const float* __restrict__ We2,
                 const float* __restrict__ be2,
                 float* __restrict__ out_attn)
{
    const int b    = blockIdx.x;
    const int tid  = threadIdx.x;
    const int lane = tid & 31;
    const int wid  = tid >> 5;

    __shared__ float s_logit[49];
    __shared__ float s_attn[49];

    const float* base = g_qkv + (size_t)b * NN * NP;
    const float* cc   = g_cc  + (size_t)b * DD;

    for (int p = wid; p < 49; p += 8) {
        const int n = p / 7, m = p % 7;
        const float* qn  = base + (size_t)n * NP + 0*DD;
        const float* km  = base + (size_t)m * NP + 1*DD;
        const float* lan = base + (size_t)n * NP + 3*DD;
        const float* rbm = base + (size_t)m * NP + 4*DD;
        float qk = 0.0f, e = 0.0f;
        for (int d = lane; d < DD; d += 32) {
            qk = fmaf(qn[d], km[d], qk);
            float h = lan[d] + rbm[d] + cc[d] + be1[d];
            e  = fmaf(geluf(h), We2[d], e);
        }
        #pragma unroll
        for (int o = 16; o > 0; o >>= 1) {
            qk += __shfl_down_sync(0xffffffffu, qk, o);
            e  += __shfl_down_sync(0xffffffffu, e,  o);
        }
        if (lane == 0)
            s_logit[p] = qk * (1.0f / 32.0f) + e + be2[0]
                       + (c_adj[p] - 1.0f) * 10000.0f;
    }
    __syncthreads();

    if (tid < 7) {
        const int n = tid;
        float mx = -1e30f;
        #pragma unroll
        for (int m = 0; m < 7; m++) mx = fmaxf(mx, s_logit[n * 7 + m]);
        float ex[7], s = 0.0f;
        #pragma unroll
        for (int m = 0; m < 7; m++) { ex[m] = expf(s_logit[n * 7 + m] - mx); s += ex[m]; }
        #pragma unroll
        for (int m = 0; m < 7; m++) {
            float a = ex[m] / s;
            s_attn[n * 7 + m] = a;
            out_attn[(size_t)b * 49 + n * 7 + m] = a;
        }
    }
    __syncthreads();

    float* msg = g_msg + (size_t)b * NN * DD;
    for (int d = tid; d < DD; d += 256) {
        float vv[7];
        #pragma unroll
        for (int m = 0; m < 7; m++) vv[m] = base[(size_t)m * NP + 2*DD + d];
        #pragma unroll
        for (int n = 0; n < 7; n++) {
            float acc = 0.0f;
            #pragma unroll
            for (int m = 0; m < 7; m++) acc = fmaf(s_attn[n * 7 + m], vv[m], acc);
            msg[n * DD + d] = acc;
        }
    }
}

// g_cat = [nodes | g_msg]
__global__ void concat_nm_kernel(const float* __restrict__ nodes)
{
    size_t i = (size_t)blockIdx.x * blockDim.x + threadIdx.x;
    if (i >= (size_t)MM * DD) return;
    size_t row = i / DD, d = i % DD;
    g_cat[row * 2 * DD + d]      = nodes[i];
    g_cat[row * 2 * DD + DD + d] = g_msg[i];
}

// g_cat = [updated | updated[b, N-1] broadcast]
__global__ void concat_ug_kernel(const float* __restrict__ upd)
{
    size_t i = (size_t)blockIdx.x * blockDim.x + threadIdx.x;
    if (i >= (size_t)MM * DD) return;
    size_t row = i / DD, d = i % DD;
    size_t b = row / NN;
    g_cat[row * 2 * DD + d]      = upd[i];
    g_cat[row * 2 * DD + DD + d] = upd[(b * NN + (NN - 1)) * (size_t)DD + d];
}

// imp_logits = g_hid @ Wi2 + bi2
__global__ __launch_bounds__(128)
void gemv_imp_kernel(const float* __restrict__ Wi2, const float* __restrict__ bi2)
{
    const int row = blockIdx.x;
    const int tid = threadIdx.x;
    const float* h = g_hid + (size_t)row * DD;
    float s = 0.0f;
    for (int d = tid; d < DD; d += 128) s = fmaf(h[d], Wi2[d], s);
    #pragma unroll
    for (int o = 16; o > 0; o >>= 1) s += __shfl_down_sync(0xffffffffu, s, o);
    __shared__ float red[4];
    if ((tid & 31) == 0) red[tid >> 5] = s;
    __syncthreads();
    if (tid == 0)
        g_implog[row] = red[0] + red[1] + red[2] + red[3] + bi2[0];
}

// softmax over N + _cap_importance
__global__ void imp_kernel(float* __restrict__ out_imp)
{
    const int b = blockIdx.x;
    if (threadIdx.x != 0) return;
    float l[7], mx = -1e30f;
    #pragma unroll
    for (int n = 0; n < 7; n++) { l[n] = g_implog[b * 7 + n]; mx = fmaxf(mx, l[n]); }
    float s = 0.0f;
    #pragma unroll
    for (int n = 0; n < 7; n++) { l[n] = expf(l[n] - mx); s += l[n]; }
    float imp[7];
    #pragma unroll
    for (int n = 0; n < 7; n++) imp[n] = l[n] / s;

    const float cap[7] = {1.f,1.f,1.f,0.26f,1.f,1.f,0.24f};
    const float fr [7] = {1.f,1.f,1.f,0.f,  1.f,1.f,0.f };
    float capped[7], sc = 0.0f, fm = 0.0f;
    #pragma unroll
    for (int n = 0; n < 7; n++) {
        capped[n] = fminf(imp[n], cap[n]);
        sc += capped[n];
        fm += imp[n] * fr[n];
    }
    float residual = fmaxf(1.0f - sc, 0.0f);
    float redis[7], sr = 0.0f;
    #pragma unroll
    for (int n = 0; n < 7; n++) {
        float fs = (fm > 1e-6f) ? imp[n] * fr[n] / fmaxf(fm, 1e-6f) : fr[n] / 5.0f;
        redis[n] = capped[n] + fs * residual;
        sr += redis[n];
    }
    #pragma unroll
    for (int n = 0; n < 7; n++)
        out_imp[b * 7 + n] = redis[n] / fmaxf(sr, 1e-6f);
}

// fused[b,d] = sum_n imp[b,n] * updated[b,n,d]
__global__ __launch_bounds__(256)
void fused_kernel(const float* __restrict__ out_imp,
                  const float* __restrict__ upd,
                  float* __restrict__ out_fused)
{
    const int b = blockIdx.x;
    const int tid = threadIdx.x;
    __shared__ float w[7];
    if (tid < 7) w[tid] = out_imp[b * 7 + tid];
    __syncthreads();
    const float* u = upd + (size_t)b * NN * DD;
    for (int d = tid; d < DD; d += 256) {
        float acc = 0.0f;
        #pragma unroll
        for (int n = 0; n < 7; n++) acc = fmaf(w[n], u[n * DD + d], acc);
        out_fused[(size_t)b * DD + d] = acc;
    }
}

// physics + alignment partials per batch
__global__ __launch_bounds__(256)
void physalign_kernel(const float* __restrict__ upd,
                      const float* __restrict__ fused)
{
    const int b = blockIdx.x;
    const int tid = threadIdx.x;
    const int lane = tid & 31, wid = tid >> 5;
    __shared__ float dots[57];
    const float* u = upd   + (size_t)b * NN * DD;
    const float* f = fused + (size_t)b * DD;

    for (int t = wid; t < 57; t += 8) {
        const float *x, *y;
        if (t < 49)      { x = u + (t / 7) * DD; y = u + (t % 7) * DD; }
        else if (t < 56) { x = u + (t - 49) * DD; y = f; }
        else             { x = f; y = f; }
        float s = 0.0f;
        for (int d = lane; d < DD; d += 32) s = fmaf(x[d], y[d], s);
        #pragma unroll
        for (int o = 16; o > 0; o >>= 1) s += __shfl_down_sync(0xffffffffu, s, o);
        if (lane == 0) dots[t] = s;
    }
    __syncthreads();

    if (tid == 0) {
        float norms[7];
        #pragma unroll
        for (int n = 0; n < 7; n++) norms[n] = sqrtf(dots[n * 7 + n]);
        float edge = 0.0f, non = 0.0f;
        #pragma unroll
        for (int n = 0; n < 7; n++) {
            #pragma unroll
            for (int m = 0; m < 7; m++) {
                float cs = dots[n * 7 + m] / fmaxf(norms[n] * norms[m], 1e-8f);
                float a = c_adj[n * 7 + m];
                edge += (1.0f - cs) * a;
                float nonmask = (1.0f - a) * ((n == m) ? 0.0f : 1.0f);
                non += fmaxf(cs - 0.35f, 0.0f) * nonmask;
            }
        }
        g_phys_part[b] = edge / 41.0f + 0.5f * non / 8.0f;

        float fn = sqrtf(dots[56]);
        float al = 0.0f;
        #pragma unroll
        for (int n = 0; n < 7; n++) {
            float cs = dots[49 + n] / (fmaxf(norms[n], 1e-12f) * fmaxf(fn, 1e-12f));
            al += 1.0f - cs;
        }
        g_align_part[b] = al;
    }
}

// deterministic final reduction -> scalars
__global__ __launch_bounds__(256)
void final_reduce_kernel(float* __restrict__ out)
{
    const int tid = threadIdx.x;
    float p = 0.0f, a = 0.0f;
    for (int b = tid; b < BB; b += 256) { p += g_phys_part[b]; a += g_align_part[b]; }
    __shared__ float sp[256], sa[256];
    sp[tid] = p; sa[tid] = a;
    __syncthreads();
    for (int s = 128; s > 0; s >>= 1) {
        if (tid < s) { sp[tid] += sp[tid + s]; sa[tid] += sa[tid + s]; }
        __syncthreads();
    }
    if (tid == 0) {
        out[OFF_PHYS]  = sp[0];
        out[OFF_ALIGN] = sa[0] / (float)(BB * NN);
    }
}

// ---------------------------------------------------------------------------
extern "C" void kernel_launch(void* const* d_in, const int* in_sizes, int n_in,
                              void* d_out, int out_size)
{
    const float* nodes = (const float*)d_in[0];
    const float* Wq    = (const float*)d_in[1];
    const float* bq    = (const float*)d_in[2];
    const float* Wk    = (const float*)d_in[3];
    const float* bk    = (const float*)d_in[4];
    const float* Wv    = (const float*)d_in[5];
    const float* bv    = (const float*)d_in[6];
    const float* We1   = (const float*)d_in[7];
    const float* be1   = (const float*)d_in[8];
    const float* We2   = (const float*)d_in[9];
    const float* be2   = (const float*)d_in[10];
    const float* Wu1   = (const float*)d_in[11];
    const float* bu1   = (const float*)d_in[12];
    const float* Wu2   = (const float*)d_in[13];
    const float* bu2   = (const float*)d_in[14];
    const float* Wi1   = (const float*)d_in[15];
    const float* bi1   = (const float*)d_in[16];
    const float* Wi2   = (const float*)d_in[17];
    const float* bi2   = (const float*)d_in[18];

    float* out       = (float*)d_out;
    float* out_fused = out + OFF_FUSED;
    float* out_upd   = out + OFF_UPD;
    float* out_imp   = out + OFF_IMP;
    float* out_attn  = out + OFF_ATTN;

    float* qkv  = nullptr; cudaGetSymbolAddress((void**)&qkv,  g_qkv);
    float* wpk  = nullptr; cudaGetSymbolAddress((void**)&wpk,  g_wpack);
    float* bpk  = nullptr; cudaGetSymbolAddress((void**)&bpk,  g_bpack);
    float* cc   = nullptr; cudaGetSymbolAddress((void**)&cc,   g_cc);
    float* cat  = nullptr; cudaGetSymbolAddress((void**)&cat,  g_cat);
    float* hid  = nullptr; cudaGetSymbolAddress((void**)&hid,  g_hid);

    cudaFuncSetAttribute(gemm_tc_kernel,
                         cudaFuncAttributeMaxDynamicSharedMemorySize,
                         SMEM_GEMM_BYTES);

    dim3 blk(256);
    const size_t shm = SMEM_GEMM_BYTES;

    // pack merged projection weights/bias
    {
        size_t n = (size_t)DD * NP;
        pack_w_kernel<<<(unsigned)((n + 255) / 256), blk>>>(Wq, Wk, Wv, We1);
        pack_b_kernel<<<(NP + 255) / 256, blk>>>(bq, bk, bv);
    }

    // merged projections: [7168,1024] x [1024,5120] -> g_qkv
    dim3 grid_proj(NP / 128, MM / 128);     // 40 x 56
    gemm_tc_kernel<<<grid_proj, blk, shm>>>(MM, NP, DD, nodes, DD, wpk, bpk,
                                            nullptr, qkv, 0);
    // cc projection: last node rows only
    dim3 grid_cc(DD / 128, BB / 128);       // 8 x 8
    gemm_tc_kernel<<<grid_cc, blk, shm>>>(BB, DD, DD, nodes + (size_t)(NN - 1) * DD,
                                          NN * DD, We1 + (size_t)2 * DD * DD,
                                          nullptr, nullptr, cc, 0);

    // edge MLP + attention + messages
    attn_kernel<<<BB, blk>>>(be1, We2, be2, out_attn);

    // update MLP
    dim3 grid_big(DD / 128, MM / 128);      // 8 x 56
    int nconcat = (int)(((size_t)MM * DD + 255) / 256);
    concat_nm_kernel<<<nconcat, blk>>>(nodes);
    gemm_tc_kernel<<<grid_big, blk, shm>>>(MM, DD, 2 * DD, cat, 2 * DD, Wu1, bu1, nullptr, hid, 1);
    gemm_tc_kernel<<<grid_big, blk, shm>>>(MM, DD, DD, hid, DD, Wu2, bu2, nodes, out_upd, 0);

    // importance MLP
    concat_ug_kernel<<<nconcat, blk>>>(out_upd);
    gemm_tc_kernel<<<grid_big, blk, shm>>>(MM, DD, 2 * DD, cat, 2 * DD, Wi1, bi1, nullptr, hid, 1);
    gemv_imp_kernel<<<MM, 128>>>(Wi2, bi2);
    imp_kernel<<<BB, 32>>>(out_imp);

    // fused output + losses
    fused_kernel<<<BB, blk>>>(out_imp, out_upd, out_fused);
    physalign_kernel<<<BB, blk>>>(out_upd, out_fused);
    final_reduce_kernel<<<1, blk>>>(out);
}

// round 5
// speedup vs baseline: 1.3059x; 1.3059x over previous
#include <cuda_runtime.h>
#include <math.h>
#include <stdint.h>

// ---------------------------------------------------------------------------
// PhysicsGraphFusion: B=1024 graphs, N=7 nodes, D=1024 dim.
// Round 4: R2-proven 3xTF32 mma inner loop + double-buffered smem
// (1 barrier/chunk, LDG latency hidden under mma) + merged 5-way projection.
// ---------------------------------------------------------------------------

#define BB   1024
#define NN   7
#define DD   1024
#define MM   (BB*NN)          // 7168
#define NP   (5*DD)           // 5120 packed projection width

static const size_t OFF_FUSED = 0;
static const size_t OFF_UPD   = (size_t)BB*DD;
static const size_t OFF_IMP   = OFF_UPD + (size_t)MM*DD;
static const size_t OFF_ATTN  = OFF_IMP + (size_t)MM;
static const size_t OFF_PHYS  = OFF_ATTN + (size_t)BB*NN*NN;
static const size_t OFF_ALIGN = OFF_PHYS + 1;

// ---------------- device scratch (static; no runtime allocation) -----------
__device__ float g_qkv [ (size_t)MM*NP ];      // q|k|v|la|rb packed, stride 5120
__device__ float g_wpack[ (size_t)DD*NP ];
__device__ float g_bpack[ NP ];
__device__ float g_cc  [ (size_t)BB*DD ];
__device__ float g_msg [ (size_t)MM*DD ];
__device__ float g_cat [ (size_t)MM*2*DD ];
__device__ float g_hid [ (size_t)MM*DD ];
__device__ float g_implog[ MM ];
__device__ float g_phys_part [ BB ];
__device__ float g_align_part[ BB ];

__constant__ float c_adj[49] = {
    1,1,0,0,1,1,1,
    1,1,1,1,1,1,1,
    0,1,1,0,1,0,1,
    0,1,0,1,1,1,1,
    1,1,1,1,1,1,1,
    1,1,0,1,1,1,1,
    1,1,1,1,1,1,1 };

__device__ __forceinline__ float geluf(float x) {
    return 0.5f * x * (1.0f + erff(x * 0.70710678118654752440f));
}

__device__ __forceinline__ float tf32_rna(float x) {
    float r;
    asm("cvt.rna.tf32.f32 %0, %1;" : "=f"(r) : "f"(x));
    return r;
}

__device__ __forceinline__ void mma_tf32(float* c,
    uint32_t a0, uint32_t a1, uint32_t a2, uint32_t a3,
    uint32_t b0, uint32_t b1)
{
    asm volatile(
        "mma.sync.aligned.m16n8k8.row.col.f32.tf32.tf32.f32 "
        "{%0,%1,%2,%3}, {%4,%5,%6,%7}, {%8,%9}, {%0,%1,%2,%3};\n"
        : "+f"(c[0]), "+f"(c[1]), "+f"(c[2]), "+f"(c[3])
        : "r"(a0), "r"(a1), "r"(a2), "r"(a3), "r"(b0), "r"(b1));
}

// ---------------------------------------------------------------------------
// Tensor-core GEMM: C[M,Nc] = epi(A[M,K] @ W[K,Nc] + bias), 3xTF32.
// BM=BN=128, BK=32, 256 threads (8 warps, 4x2), warp tile 32x64.
// Double-buffered smem, R2-proven hi/lo layout:
//   per buffer: As_h[128][36], As_l[128][36], Bs_h[32][136], Bs_l[32][136]
// ---------------------------------------------------------------------------
#define AS_STRIDE 36
#define BS_STRIDE 136
#define BUF_FLOATS (2*128*AS_STRIDE + 2*32*BS_STRIDE)   // 17920
#define SMEM_GEMM_BYTES (2*BUF_FLOATS*4)                // 143360 B

__device__ __forceinline__ void split_store(float* buf,
    const float4* pa, const float4* pb, const int* ar, const int* ac4,
    const int* br, const int* bc4)
{
    float* As_h = buf;
    float* As_l = As_h + 128 * AS_STRIDE;
    float* Bs_h = As_l + 128 * AS_STRIDE;
    float* Bs_l = Bs_h + 32 * BS_STRIDE;
    #pragma unroll
    for (int it = 0; it < 4; it++) {
        float h, l;
        int ai = ar[it] * AS_STRIDE + ac4[it];
        h = tf32_rna(pa[it].x); l = tf32_rna(pa[it].x - h);
        As_h[ai + 0] = h; As_l[ai + 0] = l;
        h = tf32_rna(pa[it].y); l = tf32_rna(pa[it].y - h);
        As_h[ai + 1] = h; As_l[ai + 1] = l;
        h = tf32_rna(pa[it].z); l = tf32_rna(pa[it].z - h);
        As_h[ai + 2] = h; As_l[ai + 2] = l;
        h = tf32_rna(pa[it].w); l = tf32_rna(pa[it].w - h);
        As_h[ai + 3] = h; As_l[ai + 3] = l;

        int bi = br[it] * BS_STRIDE + bc4[it];
        h = tf32_rna(pb[it].x); l = tf32_rna(pb[it].x - h);
        Bs_h[bi + 0] = h; Bs_l[bi + 0] = l;
        h = tf32_rna(pb[it].y); l = tf32_rna(pb[it].y - h);
        Bs_h[bi + 1] = h; Bs_l[bi + 1] = l;
        h = tf32_rna(pb[it].z); l = tf32_rna(pb[it].z - h);
        Bs_h[bi + 2] = h; Bs_l[bi + 2] = l;
        h = tf32_rna(pb[it].w); l = tf32_rna(pb[it].w - h);
        Bs_h[bi + 3] = h; Bs_l[bi + 3] = l;
    }
}

__global__ __launch_bounds__(256)
void gemm_tc_kernel(int M, int Nc, int K,
                    const float* __restrict__ A, int lda,
                    const float* __restrict__ W,
                    const float* __restrict__ bias,
                    const float* __restrict__ resid,
                    float* __restrict__ C,
                    int applyGelu)
{
    extern __shared__ float smem[];

    const int tid  = threadIdx.x;
    const int lane = tid & 31;
    const int wid  = tid >> 5;
    const int wm   = wid & 3;
    const int wn   = wid >> 2;
    const int gid  = lane >> 2;
    const int tig  = lane & 3;

    const int brow = blockIdx.y;
    const int bcol = blockIdx.x;

    const float* Aptr = A + (size_t)(brow * 128) * lda;
    const float* Wptr = W + (size_t)bcol * 128;

    int ar[4], ac4[4], br[4], bc4[4];
    #pragma unroll
    for (int it = 0; it < 4; it++) {
        int idx = it * 256 + tid;
        ar[it]  = idx >> 3;  ac4[it] = (idx & 7) * 4;
        br[it]  = idx >> 5;  bc4[it] = (idx & 31) * 4;
    }

    float acc[2][8][4];
    #pragma unroll
    for (int mi = 0; mi < 2; mi++)
        #pragma unroll
        for (int ni = 0; ni < 8; ni++)
            #pragma unroll
            for (int r = 0; r < 4; r++) acc[mi][ni][r] = 0.0f;

    // preload chunk 0 and store into buffer 0
    float4 pa[4], pb[4];
    #pragma unroll
    for (int it = 0; it < 4; it++) {
        pa[it] = *(const float4*)(Aptr + (size_t)ar[it] * lda + ac4[it]);
        pb[it] = *(const float4*)(Wptr + (size_t)br[it] * Nc + bc4[it]);
    }
    split_store(smem, pa, pb, ar, ac4, br, bc4);
    __syncthreads();

    const int nChunks = K >> 5;
    for (int c = 0; c < nChunks; c++) {
        float* cur  = smem + (size_t)(c & 1) * BUF_FLOATS;
        float* As_h = cur;
        float* As_l = As_h + 128 * AS_STRIDE;
        float* Bs_h = As_l + 128 * AS_STRIDE;
        float* Bs_l = Bs_h + 32 * BS_STRIDE;

        // issue global loads for next chunk (latency hidden by mma below)
        bool more = (c + 1 < nChunks);
        if (more) {
            int k0 = (c + 1) << 5;
            #pragma unroll
            for (int it = 0; it < 4; it++) {
                pa[it] = *(const float4*)(Aptr + (size_t)ar[it] * lda + k0 + ac4[it]);
                pb[it] = *(const float4*)(Wptr + (size_t)(k0 + br[it]) * Nc + bc4[it]);
            }
        }

        // ---- compute (R2-proven inner loop) ----
        #pragma unroll
        for (int kk = 0; kk < 4; kk++) {
            uint32_t ah[2][4], al[2][4];
            #pragma unroll
            for (int mi = 0; mi < 2; mi++) {
                int r0 = (wm * 32 + mi * 16 + gid) * AS_STRIDE + kk * 8 + tig;
                ah[mi][0] = __float_as_uint(As_h[r0]);
                ah[mi][1] = __float_as_uint(As_h[r0 + 8 * AS_STRIDE]);
                ah[mi][2] = __float_as_uint(As_h[r0 + 4]);
                ah[mi][3] = __float_as_uint(As_h[r0 + 8 * AS_STRIDE + 4]);
                al[mi][0] = __float_as_uint(As_l[r0]);
                al[mi][1] = __float_as_uint(As_l[r0 + 8 * AS_STRIDE]);
                al[mi][2] = __float_as_uint(As_l[r0 + 4]);
                al[mi][3] = __float_as_uint(As_l[r0 + 8 * AS_STRIDE + 4]);
            }
            #pragma unroll
            for (int ni = 0; ni < 8; ni++) {
                int bi = (kk * 8 + tig) * BS_STRIDE + wn * 64 + ni * 8 + gid;
                uint32_t bh0 = __float_as_uint(Bs_h[bi]);
                uint32_t bh1 = __float_as_uint(Bs_h[bi + 4 * BS_STRIDE]);
                uint32_t bl0 = __float_as_uint(Bs_l[bi]);
                uint32_t bl1 = __float_as_uint(Bs_l[bi + 4 * BS_STRIDE]);
                #pragma unroll
                for (int mi = 0; mi < 2; mi++) {
                    mma_tf32(acc[mi][ni], ah[mi][0], ah[mi][1], ah[mi][2], ah[mi][3], bh0, bh1);
                    mma_tf32(acc[mi][ni], ah[mi][0], ah[mi][1], ah[mi][2], ah[mi][3], bl0, bl1);
                    mma_tf32(acc[mi][ni], al[mi][0], al[mi][1], al[mi][2], al[mi][3], bh0, bh1);
                }
            }
        }

        // ---- store next chunk into the other buffer ----
        if (more)
            split_store(smem + (size_t)((c + 1) & 1) * BUF_FLOATS,
                        pa, pb, ar, ac4, br, bc4);
        __syncthreads();
    }

    // ---- epilogue ----
    #pragma unroll
    for (int mi = 0; mi < 2; mi++) {
        #pragma unroll
        for (int ni = 0; ni < 8; ni++) {
            int row0 = brow * 128 + wm * 32 + mi * 16 + gid;
            int col0 = bcol * 128 + wn * 64 + ni * 8 + tig * 2;
            #pragma unroll
            for (int half = 0; half < 2; half++) {
                int row = row0 + half * 8;
                size_t base = (size_t)row * Nc + col0;
                float v0 = acc[mi][ni][half * 2 + 0];
                float v1 = acc[mi][ni][half * 2 + 1];
                if (bias) { v0 += bias[col0]; v1 += bias[col0 + 1]; }
                if (applyGelu) { v0 = geluf(v0); v1 = geluf(v1); }
                if (resid) { v0 += resid[base]; v1 += resid[base + 1]; }
                C[base]     = v0;
                C[base + 1] = v1;
            }
        }
    }
}

// ---------------------------------------------------------------------------
// Weight/bias packing for the merged projection GEMM
// ---------------------------------------------------------------------------
__global__ void pack_w_kernel(const float* __restrict__ Wq,
                              const float* __restrict__ Wk,
                              const float* __restrict__ Wv,
                              const float* __restrict__ We1)
{
    size_t i = (size_t)blockIdx.x * blockDim.x + threadIdx.x;
    if (i >= (size_t)DD * NP) return;
    int r   = (int)(i / NP);
    int c   = (int)(i % NP);
    int seg = c >> 10;
    int cc  = c & 1023;
    const float* src;
    if      (seg == 0) src = Wq;
    else if (seg == 1) src = Wk;
    else if (seg == 2) src = Wv;
    else if (seg == 3) src = We1;
    else               src = We1 + (size_t)DD * DD;
    g_wpack[i] = src[(size_t)r * DD + cc];
}

__global__ void pack_b_kernel(const float* __restrict__ bq,
                              const float* __restrict__ bk,
                              const float* __restrict__ bv)
{
    int c = blockIdx.x * blockDim.x + threadIdx.x;
    if (c >= NP) return;
    int seg = c >> 10, cc = c & 1023;
    float v = 0.0f;
    if      (seg == 0) v = bq[cc];
    else if (seg == 1) v = bk[cc];
    else if (seg == 2) v = bv[cc];
    g_bpack[c] = v;
}

// ---------------------------------------------------------------------------
// Per-batch attention (reads packed g_qkv, row stride NP)
// ---------------------------------------------------------------------------
__global__ __launch_bounds__(256)
void attn_kernel(const float* __restrict__ be1,
                 const float* __restrict__ We2,
                 const float* __restrict__ be2,
                 float* __restrict__ out_attn)
{
    const int b    = blockIdx.x;
    const int tid  = threadIdx.x;
    const int lane = tid & 31;
    const int wid  = tid >> 5;

    __shared__ float s_logit[49];
    __shared__ float s_attn[49];

    const float* base = g_qkv + (size_t)b * NN * NP;
    const float* cc   = g_cc  + (size_t)b * DD;

    for (int p = wid; p < 49; p += 8) {
        const int n = p / 7, m = p % 7;
        const float* qn  = base + (size_t)n * NP + 0*DD;
        const float* km  = base + (size_t)m * NP + 1*DD;
        const float* lan = base + (size_t)n * NP + 3*DD;
        const float* rbm = base + (size_t)m * NP + 4*DD;
        float qk = 0.0f, e = 0.0f;
        for (int d = lane; d < DD; d += 32) {
            qk = fmaf(qn[d], km[d], qk);
            float h = lan[d] + rbm[d] + cc[d] + be1[d];
            e  = fmaf(geluf(h), We2[d], e);
        }
        #pragma unroll
        for (int o = 16; o > 0; o >>= 1) {
            qk += __shfl_down_sync(0xffffffffu, qk, o);
            e  += __shfl_down_sync(0xffffffffu, e,  o);
        }
        if (lane == 0)
            s_logit[p] = qk * (1.0f / 32.0f) + e + be2[0]
                       + (c_adj[p] - 1.0f) * 10000.0f;
    }
    __syncthreads();

    if (tid < 7) {
        const int n = tid;
        float mx = -1e30f;
        #pragma unroll
        for (int m = 0; m < 7; m++) mx = fmaxf(mx, s_logit[n * 7 + m]);
        float ex[7], s = 0.0f;
        #pragma unroll
        for (int m = 0; m < 7; m++) { ex[m] = expf(s_logit[n * 7 + m] - mx); s += ex[m]; }
        #pragma unroll
        for (int m = 0; m < 7; m++) {
            float a = ex[m] / s;
            s_attn[n * 7 + m] = a;
            out_attn[(size_t)b * 49 + n * 7 + m] = a;
        }
    }
    __syncthreads();

    float* msg = g_msg + (size_t)b * NN * DD;
    for (int d = tid; d < DD; d += 256) {
        float vv[7];
        #pragma unroll
        for (int m = 0; m < 7; m++) vv[m] = base[(size_t)m * NP + 2*DD + d];
        #pragma unroll
        for (int n = 0; n < 7; n++) {
            float acc = 0.0f;
            #pragma unroll
            for (int m = 0; m < 7; m++) acc = fmaf(s_attn[n * 7 + m], vv[m], acc);
            msg[n * DD + d] = acc;
        }
    }
}

// g_cat = [nodes | g_msg]
__global__ void concat_nm_kernel(const float* __restrict__ nodes)
{
    size_t i = (size_t)blockIdx.x * blockDim.x + threadIdx.x;
    if (i >= (size_t)MM * DD) return;
    size_t row = i / DD, d = i % DD;
    g_cat[row * 2 * DD + d]      = nodes[i];
    g_cat[row * 2 * DD + DD + d] = g_msg[i];
}

// g_cat = [updated | updated[b, N-1] broadcast]
__global__ void concat_ug_kernel(const float* __restrict__ upd)
{
    size_t i = (size_t)blockIdx.x * blockDim.x + threadIdx.x;
    if (i >= (size_t)MM * DD) return;
    size_t row = i / DD, d = i % DD;
    size_t b = row / NN;
    g_cat[row * 2 * DD + d]      = upd[i];
    g_cat[row * 2 * DD + DD + d] = upd[(b * NN + (NN - 1)) * (size_t)DD + d];
}

// imp_logits = g_hid @ Wi2 + bi2
__global__ __launch_bounds__(128)
void gemv_imp_kernel(const float* __restrict__ Wi2, const float* __restrict__ bi2)
{
    const int row = blockIdx.x;
    const int tid = threadIdx.x;
    const float* h = g_hid + (size_t)row * DD;
    float s = 0.0f;
    for (int d = tid; d < DD; d += 128) s = fmaf(h[d], Wi2[d], s);
    #pragma unroll
    for (int o = 16; o > 0; o >>= 1) s += __shfl_down_sync(0xffffffffu, s, o);
    __shared__ float red[4];
    if ((tid & 31) == 0) red[tid >> 5] = s;
    __syncthreads();
    if (tid == 0)
        g_implog[row] = red[0] + red[1] + red[2] + red[3] + bi2[0];
}

// softmax over N + _cap_importance
__global__ void imp_kernel(float* __restrict__ out_imp)
{
    const int b = blockIdx.x;
    if (threadIdx.x != 0) return;
    float l[7], mx = -1e30f;
    #pragma unroll
    for (int n = 0; n < 7; n++) { l[n] = g_implog[b * 7 + n]; mx = fmaxf(mx, l[n]); }
    float s = 0.0f;
    #pragma unroll
    for (int n = 0; n < 7; n++) { l[n] = expf(l[n] - mx); s += l[n]; }
    float imp[7];
    #pragma unroll
    for (int n = 0; n < 7; n++) imp[n] = l[n] / s;

    const float cap[7] = {1.f,1.f,1.f,0.26f,1.f,1.f,0.24f};
    const float fr [7] = {1.f,1.f,1.f,0.f,  1.f,1.f,0.f };
    float capped[7], sc = 0.0f, fm = 0.0f;
    #pragma unroll
    for (int n = 0; n < 7; n++) {
        capped[n] = fminf(imp[n], cap[n]);
        sc += capped[n];
        fm += imp[n] * fr[n];
    }
    float residual = fmaxf(1.0f - sc, 0.0f);
    float redis[7], sr = 0.0f;
    #pragma unroll
    for (int n = 0; n < 7; n++) {
        float fs = (fm > 1e-6f) ? imp[n] * fr[n] / fmaxf(fm, 1e-6f) : fr[n] / 5.0f;
        redis[n] = capped[n] + fs * residual;
        sr += redis[n];
    }
    #pragma unroll
    for (int n = 0; n < 7; n++)
        out_imp[b * 7 + n] = redis[n] / fmaxf(sr, 1e-6f);
}

// fused[b,d] = sum_n imp[b,n] * updated[b,n,d]
__global__ __launch_bounds__(256)
void fused_kernel(const float* __restrict__ out_imp,
                  const float* __restrict__ upd,
                  float* __restrict__ out_fused)
{
    const int b = blockIdx.x;
    const int tid = threadIdx.x;
    __shared__ float w[7];
    if (tid < 7) w[tid] = out_imp[b * 7 + tid];
    __syncthreads();
    const float* u = upd + (size_t)b * NN * DD;
    for (int d = tid; d < DD; d += 256) {
        float acc = 0.0f;
        #pragma unroll
        for (int n = 0; n < 7; n++) acc = fmaf(w[n], u[n * DD + d], acc);
        out_fused[(size_t)b * DD + d] = acc;
    }
}

// physics + alignment partials per batch
__global__ __launch_bounds__(256)
void physalign_kernel(const float* __restrict__ upd,
                      const float* __restrict__ fused)
{
    const int b = blockIdx.x;
    const int tid = threadIdx.x;
    const int lane = tid & 31, wid = tid >> 5;
    __shared__ float dots[57];
    const float* u = upd   + (size_t)b * NN * DD;
    const float* f = fused + (size_t)b * DD;

    for (int t = wid; t < 57; t += 8) {
        const float *x, *y;
        if (t < 49)      { x = u + (t / 7) * DD; y = u + (t % 7) * DD; }
        else if (t < 56) { x = u + (t - 49) * DD; y = f; }
        else             { x = f; y = f; }
        float s = 0.0f;
        for (int d = lane; d < DD; d += 32) s = fmaf(x[d], y[d], s);
        #pragma unroll
        for (int o = 16; o > 0; o >>= 1) s += __shfl_down_sync(0xffffffffu, s, o);
        if (lane == 0) dots[t] = s;
    }
    __syncthreads();

    if (tid == 0) {
        float norms[7];
        #pragma unroll
        for (int n = 0; n < 7; n++) norms[n] = sqrtf(dots[n * 7 + n]);
        float edge = 0.0f, non = 0.0f;
        #pragma unroll
        for (int n = 0; n < 7; n++) {
            #pragma unroll
            for (int m = 0; m < 7; m++) {
                float cs = dots[n * 7 + m] / fmaxf(norms[n] * norms[m], 1e-8f);
                float a = c_adj[n * 7 + m];
                edge += (1.0f - cs) * a;
                float nonmask = (1.0f - a) * ((n == m) ? 0.0f : 1.0f);
                non += fmaxf(cs - 0.35f, 0.0f) * nonmask;
            }
        }
        g_phys_part[b] = edge / 41.0f + 0.5f * non / 8.0f;

        float fn = sqrtf(dots[56]);
        float al = 0.0f;
        #pragma unroll
        for (int n = 0; n < 7; n++) {
            float cs = dots[49 + n] / (fmaxf(norms[n], 1e-12f) * fmaxf(fn, 1e-12f));
            al += 1.0f - cs;
        }
        g_align_part[b] = al;
    }
}

// deterministic final reduction -> scalars
__global__ __launch_bounds__(256)
void final_reduce_kernel(float* __restrict__ out)
{
    const int tid = threadIdx.x;
    float p = 0.0f, a = 0.0f;
    for (int b = tid; b < BB; b += 256) { p += g_phys_part[b]; a += g_align_part[b]; }
    __shared__ float sp[256], sa[256];
    sp[tid] = p; sa[tid] = a;
    __syncthreads();
    for (int s = 128; s > 0; s >>= 1) {
        if (tid < s) { sp[tid] += sp[tid + s]; sa[tid] += sa[tid + s]; }
        __syncthreads();
    }
    if (tid == 0) {
        out[OFF_PHYS]  = sp[0];
        out[OFF_ALIGN] = sa[0] / (float)(BB * NN);
    }
}

// ---------------------------------------------------------------------------
extern "C" void kernel_launch(void* const* d_in, const int* in_sizes, int n_in,
                              void* d_out, int out_size)
{
    const float* nodes = (const float*)d_in[0];
    const float* Wq    = (const float*)d_in[1];
    const float* bq    = (const float*)d_in[2];
    const float* Wk    = (const float*)d_in[3];
    const float* bk    = (const float*)d_in[4];
    const float* Wv    = (const float*)d_in[5];
    const float* bv    = (const float*)d_in[6];
    const float* We1   = (const float*)d_in[7];
    const float* be1   = (const float*)d_in[8];
    const float* We2   = (const float*)d_in[9];
    const float* be2   = (const float*)d_in[10];
    const float* Wu1   = (const float*)d_in[11];
    const float* bu1   = (const float*)d_in[12];
    const float* Wu2   = (const float*)d_in[13];
    const float* bu2   = (const float*)d_in[14];
    const float* Wi1   = (const float*)d_in[15];
    const float* bi1   = (const float*)d_in[16];
    const float* Wi2   = (const float*)d_in[17];
    const float* bi2   = (const float*)d_in[18];

    float* out       = (float*)d_out;
    float* out_fused = out + OFF_FUSED;
    float* out_upd   = out + OFF_UPD;
    float* out_imp   = out + OFF_IMP;
    float* out_attn  = out + OFF_ATTN;

    float* qkv  = nullptr; cudaGetSymbolAddress((void**)&qkv,  g_qkv);
    float* wpk  = nullptr; cudaGetSymbolAddress((void**)&wpk,  g_wpack);
    float* bpk  = nullptr; cudaGetSymbolAddress((void**)&bpk,  g_bpack);
    float* cc   = nullptr; cudaGetSymbolAddress((void**)&cc,   g_cc);
    float* cat  = nullptr; cudaGetSymbolAddress((void**)&cat,  g_cat);
    float* hid  = nullptr; cudaGetSymbolAddress((void**)&hid,  g_hid);

    cudaFuncSetAttribute(gemm_tc_kernel,
                         cudaFuncAttributeMaxDynamicSharedMemorySize,
                         SMEM_GEMM_BYTES);

    dim3 blk(256);
    const size_t shm = SMEM_GEMM_BYTES;

    // pack merged projection weights/bias
    {
        size_t n = (size_t)DD * NP;
        pack_w_kernel<<<(unsigned)((n + 255) / 256), blk>>>(Wq, Wk, Wv, We1);
        pack_b_kernel<<<(NP + 255) / 256, blk>>>(bq, bk, bv);
    }

    // merged projections: [7168,1024] x [1024,5120] -> g_qkv
    dim3 grid_proj(NP / 128, MM / 128);     // 40 x 56
    gemm_tc_kernel<<<grid_proj, blk, shm>>>(MM, NP, DD, nodes, DD, wpk, bpk,
                                            nullptr, qkv, 0);
    // cc projection: last node rows only
    dim3 grid_cc(DD / 128, BB / 128);       // 8 x 8
    gemm_tc_kernel<<<grid_cc, blk, shm>>>(BB, DD, DD, nodes + (size_t)(NN - 1) * DD,
                                          NN * DD, We1 + (size_t)2 * DD * DD,
                                          nullptr, nullptr, cc, 0);

    // edge MLP + attention + messages
    attn_kernel<<<BB, blk>>>(be1, We2, be2, out_attn);

    // update MLP
    dim3 grid_big(DD / 128, MM / 128);      // 8 x 56
    int nconcat = (int)(((size_t)MM * DD + 255) / 256);
    concat_nm_kernel<<<nconcat, blk>>>(nodes);
    gemm_tc_kernel<<<grid_big, blk, shm>>>(MM, DD, 2 * DD, cat, 2 * DD, Wu1, bu1, nullptr, hid, 1);
    gemm_tc_kernel<<<grid_big, blk, shm>>>(MM, DD, DD, hid, DD, Wu2, bu2, nodes, out_upd, 0);

    // importance MLP
    concat_ug_kernel<<<nconcat, blk>>>(out_upd);
    gemm_tc_kernel<<<grid_big, blk, shm>>>(MM, DD, 2 * DD, cat, 2 * DD, Wi1, bi1, nullptr, hid, 1);
    gemv_imp_kernel<<<MM, 128>>>(Wi2, bi2);
    imp_kernel<<<BB, 32>>>(out_imp);

    // fused output + losses
    fused_kernel<<<BB, blk>>>(out_imp, out_upd, out_fused);
    physalign_kernel<<<BB, blk>>>(out_upd, out_fused);
    final_reduce_kernel<<<1, blk>>>(out);
}

// round 6
// speedup vs baseline: 2.0252x; 1.5508x over previous
#include <cuda_runtime.h>
#include <cuda_bf16.h>
#include <math.h>
#include <stdint.h>

// ---------------------------------------------------------------------------
// PhysicsGraphFusion: B=1024 graphs, N=7 nodes, D=1024 dim.
// Round 5: split-bf16 (bf16x2, 3-pass m16n8k16) GEMMs with pre-split
// activations (bf16 hi/lo planes) and pre-packed weights (k-pair uint32
// planes). GEMM inner loop: pure LDS.32 + HMMA; loader: pure uint4 copies.
// ---------------------------------------------------------------------------

#define BB   1024
#define NN   7
#define DD   1024
#define MM   (BB*NN)          // 7168
#define NP   (5*DD)           // 5120 packed projection width

static const size_t OFF_FUSED = 0;
static const size_t OFF_UPD   = (size_t)BB*DD;
static const size_t OFF_IMP   = OFF_UPD + (size_t)MM*DD;
static const size_t OFF_ATTN  = OFF_IMP + (size_t)MM;
static const size_t OFF_PHYS  = OFF_ATTN + (size_t)BB*NN*NN;
static const size_t OFF_ALIGN = OFF_PHYS + 1;

// ---------------- device scratch (static; no runtime allocation) -----------
__device__ float    g_qkv [ (size_t)MM*NP ];
__device__ float    g_cc  [ (size_t)BB*DD ];
__device__ float    g_msg [ (size_t)MM*DD ];
__device__ float    g_hid [ (size_t)MM*DD ];
__device__ float    g_bpack[ NP ];
__device__ float    g_implog[ MM ];
__device__ float    g_phys_part [ BB ];
__device__ float    g_align_part[ BB ];

// activation planes (bf16 stored as uint32 k-pairs, row-major)
__device__ uint32_t g_nodes_h[ (size_t)MM*DD/2 ];
__device__ uint32_t g_nodes_l[ (size_t)MM*DD/2 ];
__device__ uint32_t g_cat_h  [ (size_t)MM*DD ];     // width 2048 -> 1024 u32
__device__ uint32_t g_cat_l  [ (size_t)MM*DD ];
__device__ uint32_t g_hidp_h [ (size_t)MM*DD/2 ];
__device__ uint32_t g_hidp_l [ (size_t)MM*DD/2 ];

// weight planes (k-pair packed uint32 [K/2][Nc])
__device__ uint32_t g_Wproj_h[ (size_t)(DD/2)*NP ];
__device__ uint32_t g_Wproj_l[ (size_t)(DD/2)*NP ];
__device__ uint32_t g_Wc_h   [ (size_t)(DD/2)*DD ];
__device__ uint32_t g_Wc_l   [ (size_t)(DD/2)*DD ];
__device__ uint32_t g_Wu1_h  [ (size_t)DD*DD ];     // K=2048 -> 1024 rows
__device__ uint32_t g_Wu1_l  [ (size_t)DD*DD ];
__device__ uint32_t g_Wu2_h  [ (size_t)(DD/2)*DD ];
__device__ uint32_t g_Wu2_l  [ (size_t)(DD/2)*DD ];
__device__ uint32_t g_Wi1_h  [ (size_t)DD*DD ];
__device__ uint32_t g_Wi1_l  [ (size_t)DD*DD ];

__constant__ float c_adj[49] = {
    1,1,0,0,1,1,1,
    1,1,1,1,1,1,1,
    0,1,1,0,1,0,1,
    0,1,0,1,1,1,1,
    1,1,1,1,1,1,1,
    1,1,0,1,1,1,1,
    1,1,1,1,1,1,1 };

__device__ __forceinline__ float geluf(float x) {
    return 0.5f * x * (1.0f + erff(x * 0.70710678118654752440f));
}

__device__ __forceinline__ unsigned short bf16_rn(float x) {
    __nv_bfloat16 h = __float2bfloat16(x);
    return *reinterpret_cast<unsigned short*>(&h);
}
__device__ __forceinline__ float bf16_to_f(unsigned short u) {
    __nv_bfloat16 h = *reinterpret_cast<__nv_bfloat16*>(&u);
    return __bfloat162float(h);
}
// split (x0,x1) into bf16 hi/lo pair-packed words (low 16 bits = x0)
__device__ __forceinline__ void splitpack(float x0, float x1,
                                          uint32_t& H, uint32_t& L) {
    unsigned short h0 = bf16_rn(x0), h1 = bf16_rn(x1);
    float r0 = x0 - bf16_to_f(h0);
    float r1 = x1 - bf16_to_f(h1);
    unsigned short l0 = bf16_rn(r0), l1 = bf16_rn(r1);
    H = (uint32_t)h0 | ((uint32_t)h1 << 16);
    L = (uint32_t)l0 | ((uint32_t)l1 << 16);
}

__device__ __forceinline__ void mma_bf16(float* c,
    uint32_t a0, uint32_t a1, uint32_t a2, uint32_t a3,
    uint32_t b0, uint32_t b1)
{
    asm volatile(
        "mma.sync.aligned.m16n8k16.row.col.f32.bf16.bf16.f32 "
        "{%0,%1,%2,%3}, {%4,%5,%6,%7}, {%8,%9}, {%0,%1,%2,%3};\n"
        : "+f"(c[0]), "+f"(c[1]), "+f"(c[2]), "+f"(c[3])
        : "r"(a0), "r"(a1), "r"(a2), "r"(a3), "r"(b0), "r"(b1));
}

// ---------------------------------------------------------------------------
// bf16x2 tensor-core GEMM. C[M,Nc] = epi(A[M,K] @ W[K,Nc] + bias).
// BM=BN=128, BK=32, 256 threads (8 warps 4x2), warp tile 32x64.
// A planes: global bf16[M][K] viewed as uint32[M][K/2]. B planes: uint32[K/2][Nc].
// smem/buffer: Ah[128][20] Al[128][20] Bh[16][136] Bl[16][136] (uint32 words).
// ---------------------------------------------------------------------------
#define A_ST 20
#define B_ST 136
#define A_PL (128*A_ST)           // 2560
#define B_PL (16*B_ST)            // 2176
#define BUF_U32 (2*A_PL + 2*B_PL) // 9472
#define SMEM_GEMM_BYTES (2*BUF_U32*4)  // 75776

__global__ __launch_bounds__(256)
void gemm_bf16x2_kernel(int M, int Nc, int K,
    const uint32_t* __restrict__ Ah, const uint32_t* __restrict__ Al, int lda32,
    const uint32_t* __restrict__ Bh, const uint32_t* __restrict__ Bl,
    const float* __restrict__ bias,
    const float* __restrict__ resid,
    float* __restrict__ Cf,
    uint32_t* __restrict__ ChH, uint32_t* __restrict__ ChL,
    int applyGelu)
{
    extern __shared__ uint32_t smem[];

    const int tid  = threadIdx.x;
    const int lane = tid & 31;
    const int wid  = tid >> 5;
    const int wm   = wid & 3;
    const int wn   = wid >> 2;
    const int gid  = lane >> 2;
    const int tig  = lane & 3;

    const int brow = blockIdx.y;
    const int bcol = blockIdx.x;

    // loader coordinates
    int apl[4], arw[4], ac4[4];       // A: plane, row, col4
    int bpl[4], bkp[4], bc4[4];       // B: plane, kpair, col4
    #pragma unroll
    for (int it = 0; it < 4; it++) {
        int idx = it * 256 + tid;     // 0..1023
        apl[it] = idx >> 9;
        int s   = idx & 511;
        arw[it] = s >> 2;  ac4[it] = (s & 3) << 2;
        bpl[it] = idx >> 9;
        bkp[it] = s >> 5;  bc4[it] = (s & 31) << 2;
    }

    const uint32_t* Asrc[2] = { Ah + (size_t)(brow * 128) * lda32,
                                Al + (size_t)(brow * 128) * lda32 };
    const uint32_t* Bsrc[2] = { Bh + bcol * 128, Bl + bcol * 128 };

    float acc[2][8][4];
    #pragma unroll
    for (int mi = 0; mi < 2; mi++)
        #pragma unroll
        for (int ni = 0; ni < 8; ni++)
            #pragma unroll
            for (int r = 0; r < 4; r++) acc[mi][ni][r] = 0.0f;

    uint4 pA[4], pB[4];
    #pragma unroll
    for (int it = 0; it < 4; it++) {
        pA[it] = *(const uint4*)(Asrc[apl[it]] + (size_t)arw[it] * lda32 + ac4[it]);
        pB[it] = *(const uint4*)(Bsrc[bpl[it]] + (size_t)bkp[it] * Nc + bc4[it]);
    }
    // store chunk 0 into buffer 0
    #pragma unroll
    for (int it = 0; it < 4; it++) {
        *(uint4*)&smem[apl[it] * A_PL + arw[it] * A_ST + ac4[it]] = pA[it];
        *(uint4*)&smem[2 * A_PL + bpl[it] * B_PL + bkp[it] * B_ST + bc4[it]] = pB[it];
    }
    __syncthreads();

    const int nChunks = K >> 5;
    for (int c = 0; c < nChunks; c++) {
        uint32_t* buf = smem + (size_t)(c & 1) * BUF_U32;
        const uint32_t* sAh = buf;
        const uint32_t* sAl = buf + A_PL;
        const uint32_t* sBh = buf + 2 * A_PL;
        const uint32_t* sBl = buf + 2 * A_PL + B_PL;

        bool more = (c + 1 < nChunks);
        if (more) {
            int kb32 = ((c + 1) << 5) >> 1;   // uint32 col base
            #pragma unroll
            for (int it = 0; it < 4; it++) {
                pA[it] = *(const uint4*)(Asrc[apl[it]] + (size_t)arw[it] * lda32 + kb32 + ac4[it]);
                pB[it] = *(const uint4*)(Bsrc[bpl[it]] + (size_t)(kb32 + bkp[it]) * Nc + bc4[it]);
            }
        }

        #pragma unroll
        for (int ks = 0; ks < 2; ks++) {
            uint32_t fah[2][4], fal[2][4];
            #pragma unroll
            for (int mi = 0; mi < 2; mi++) {
                int r0 = (wm * 32 + mi * 16 + gid) * A_ST + ks * 8 + tig;
                fah[mi][0] = sAh[r0];
                fah[mi][1] = sAh[r0 + 8 * A_ST];
                fah[mi][2] = sAh[r0 + 4];
                fah[mi][3] = sAh[r0 + 8 * A_ST + 4];
                fal[mi][0] = sAl[r0];
                fal[mi][1] = sAl[r0 + 8 * A_ST];
                fal[mi][2] = sAl[r0 + 4];
                fal[mi][3] = sAl[r0 + 8 * A_ST + 4];
            }
            #pragma unroll
            for (int ni = 0; ni < 8; ni++) {
                int nn = wn * 64 + ni * 8 + gid;
                int kb = (ks * 8 + tig) * B_ST + nn;
                uint32_t bh0 = sBh[kb];
                uint32_t bh1 = sBh[kb + 4 * B_ST];
                uint32_t bl0 = sBl[kb];
                uint32_t bl1 = sBl[kb + 4 * B_ST];
                #pragma unroll
                for (int mi = 0; mi < 2; mi++) {
                    mma_bf16(acc[mi][ni], fah[mi][0], fah[mi][1], fah[mi][2], fah[mi][3], bh0, bh1);
                    mma_bf16(acc[mi][ni], fah[mi][0], fah[mi][1], fah[mi][2], fah[mi][3], bl0, bl1);
                    mma_bf16(acc[mi][ni], fal[mi][0], fal[mi][1], fal[mi][2], fal[mi][3], bh0, bh1);
                }
            }
        }

        if (more) {
            uint32_t* nbuf = smem + (size_t)((c + 1) & 1) * BUF_U32;
            #pragma unroll
            for (int it = 0; it < 4; it++) {
                *(uint4*)&nbuf[apl[it] * A_PL + arw[it] * A_ST + ac4[it]] = pA[it];
                *(uint4*)&nbuf[2 * A_PL + bpl[it] * B_PL + bkp[it] * B_ST + bc4[it]] = pB[it];
            }
        }
        __syncthreads();
    }

    // ---- epilogue ----
    const int Nc2 = Nc >> 1;
    #pragma unroll
    for (int mi = 0; mi < 2; mi++) {
        #pragma unroll
        for (int ni = 0; ni < 8; ni++) {
            int row0 = brow * 128 + wm * 32 + mi * 16 + gid;
            int col0 = bcol * 128 + wn * 64 + ni * 8 + tig * 2;
            #pragma unroll
            for (int half = 0; half < 2; half++) {
                int row = row0 + half * 8;
                size_t base = (size_t)row * Nc + col0;
                float v0 = acc[mi][ni][half * 2 + 0];
                float v1 = acc[mi][ni][half * 2 + 1];
                if (bias) { v0 += bias[col0]; v1 += bias[col0 + 1]; }
                if (applyGelu) { v0 = geluf(v0); v1 = geluf(v1); }
                if (resid) { v0 += resid[base]; v1 += resid[base + 1]; }
                if (Cf) { Cf[base] = v0; Cf[base + 1] = v1; }
                if (ChH) {
                    uint32_t H, L;
                    splitpack(v0, v1, H, L);
                    size_t pidx = (size_t)row * Nc2 + (col0 >> 1);
                    ChH[pidx] = H;
                    ChL[pidx] = L;
                }
            }
        }
    }
}

// ---------------------------------------------------------------------------
// pre-split / pack kernels
// ---------------------------------------------------------------------------
__global__ void split_nodes_kernel(const float* __restrict__ nodes)
{
    size_t i = (size_t)blockIdx.x * blockDim.x + threadIdx.x;
    if (i >= (size_t)MM * DD / 2) return;
    float x0 = nodes[2 * i], x1 = nodes[2 * i + 1];
    splitpack(x0, x1, g_nodes_h[i], g_nodes_l[i]);
}

__global__ void pack_proj_w_kernel(const float* __restrict__ Wq,
                                   const float* __restrict__ Wk,
                                   const float* __restrict__ Wv,
                                   const float* __restrict__ We1)
{
    size_t i = (size_t)blockIdx.x * blockDim.x + threadIdx.x;
    if (i >= (size_t)(DD / 2) * NP) return;
    int kp = (int)(i / NP);
    int c  = (int)(i % NP);
    int seg = c >> 10, cc = c & 1023;
    const float* src;
    if      (seg == 0) src = Wq;
    else if (seg == 1) src = Wk;
    else if (seg == 2) src = Wv;
    else if (seg == 3) src = We1;
    else               src = We1 + (size_t)DD * DD;
    float w0 = src[(size_t)(2 * kp) * DD + cc];
    float w1 = src[(size_t)(2 * kp + 1) * DD + cc];
    splitpack(w0, w1, g_Wproj_h[i], g_Wproj_l[i]);
}

__global__ void pack_w_gen_kernel(const float* __restrict__ W, int K, int Nc,
                                  uint32_t* __restrict__ H, uint32_t* __restrict__ L)
{
    size_t i = (size_t)blockIdx.x * blockDim.x + threadIdx.x;
    if (i >= (size_t)(K / 2) * Nc) return;
    int kp = (int)(i / Nc);
    int n  = (int)(i % Nc);
    float w0 = W[(size_t)(2 * kp) * Nc + n];
    float w1 = W[(size_t)(2 * kp + 1) * Nc + n];
    splitpack(w0, w1, H[i], L[i]);
}

__global__ void pack_b_kernel(const float* __restrict__ bq,
                              const float* __restrict__ bk,
                              const float* __restrict__ bv)
{
    int c = blockIdx.x * blockDim.x + threadIdx.x;
    if (c >= NP) return;
    int seg = c >> 10, cc = c & 1023;
    float v = 0.0f;
    if      (seg == 0) v = bq[cc];
    else if (seg == 1) v = bk[cc];
    else if (seg == 2) v = bv[cc];
    g_bpack[c] = v;
}

// cat planes = split([nodes | msg]) width 2048
__global__ void concat_nm_kernel(const float* __restrict__ nodes)
{
    size_t i = (size_t)blockIdx.x * blockDim.x + threadIdx.x;
    if (i >= (size_t)MM * DD) return;          // pairs: MM*2048/2
    size_t row = i / DD;
    int dp = (int)(i % DD);                     // pair index 0..1023
    size_t srcbase = row * DD;
    float x0, x1;
    if (dp < DD / 2) { x0 = nodes[srcbase + 2 * dp];      x1 = nodes[srcbase + 2 * dp + 1]; }
    else { int d2 = 2 * dp - DD; x0 = g_msg[srcbase + d2]; x1 = g_msg[srcbase + d2 + 1]; }
    splitpack(x0, x1, g_cat_h[row * DD + dp], g_cat_l[row * DD + dp]);
}

// cat planes = split([updated | updated[b,N-1] broadcast])
__global__ void concat_ug_kernel(const float* __restrict__ upd)
{
    size_t i = (size_t)blockIdx.x * blockDim.x + threadIdx.x;
    if (i >= (size_t)MM * DD) return;
    size_t row = i / DD;
    int dp = (int)(i % DD);
    size_t b = row / NN;
    float x0, x1;
    if (dp < DD / 2) {
        x0 = upd[row * DD + 2 * dp]; x1 = upd[row * DD + 2 * dp + 1];
    } else {
        int d2 = 2 * dp - DD;
        size_t gr = (b * NN + (NN - 1)) * (size_t)DD;
        x0 = upd[gr + d2]; x1 = upd[gr + d2 + 1];
    }
    splitpack(x0, x1, g_cat_h[row * DD + dp], g_cat_l[row * DD + dp]);
}

// ---------------------------------------------------------------------------
// attention / small kernels (unchanged from R4)
// ---------------------------------------------------------------------------
__global__ __launch_bounds__(256)
void attn_kernel(const float* __restrict__ be1,
                 const float* __restrict__ We2,
                 const float* __restrict__ be2,
                 float* __restrict__ out_attn)
{
    const int b    = blockIdx.x;
    const int tid  = threadIdx.x;
    const int lane = tid & 31;
    const int wid  = tid >> 5;

    __shared__ float s_logit[49];
    __shared__ float s_attn[49];

    const float* base = g_qkv + (size_t)b * NN * NP;
    const float* cc   = g_cc  + (size_t)b * DD;

    for (int p = wid; p < 49; p += 8) {
        const int n = p / 7, m = p % 7;
        const float* qn  = base + (size_t)n * NP + 0*DD;
        const float* km  = base + (size_t)m * NP + 1*DD;
        const float* lan = base + (size_t)n * NP + 3*DD;
        const float* rbm = base + (size_t)m * NP + 4*DD;
        float qk = 0.0f, e = 0.0f;
        for (int d = lane; d < DD; d += 32) {
            qk = fmaf(qn[d], km[d], qk);
            float h = lan[d] + rbm[d] + cc[d] + be1[d];
            e  = fmaf(geluf(h), We2[d], e);
        }
        #pragma unroll
        for (int o = 16; o > 0; o >>= 1) {
            qk += __shfl_down_sync(0xffffffffu, qk, o);
            e  += __shfl_down_sync(0xffffffffu, e,  o);
        }
        if (lane == 0)
            s_logit[p] = qk * (1.0f / 32.0f) + e + be2[0]
                       + (c_adj[p] - 1.0f) * 10000.0f;
    }
    __syncthreads();

    if (tid < 7) {
        const int n = tid;
        float mx = -1e30f;
        #pragma unroll
        for (int m = 0; m < 7; m++) mx = fmaxf(mx, s_logit[n * 7 + m]);
        float ex[7], s = 0.0f;
        #pragma unroll
        for (int m = 0; m < 7; m++) { ex[m] = expf(s_logit[n * 7 + m] - mx); s += ex[m]; }
        #pragma unroll
        for (int m = 0; m < 7; m++) {
            float a = ex[m] / s;
            s_attn[n * 7 + m] = a;
            out_attn[(size_t)b * 49 + n * 7 + m] = a;
        }
    }
    __syncthreads();

    float* msg = g_msg + (size_t)b * NN * DD;
    for (int d = tid; d < DD; d += 256) {
        float vv[7];
        #pragma unroll
        for (int m = 0; m < 7; m++) vv[m] = base[(size_t)m * NP + 2*DD + d];
        #pragma unroll
        for (int n = 0; n < 7; n++) {
            float acc = 0.0f;
            #pragma unroll
            for (int m = 0; m < 7; m++) acc = fmaf(s_attn[n * 7 + m], vv[m], acc);
            msg[n * DD + d] = acc;
        }
    }
}

__global__ __launch_bounds__(128)
void gemv_imp_kernel(const float* __restrict__ Wi2, const float* __restrict__ bi2)
{
    const int row = blockIdx.x;
    const int tid = threadIdx.x;
    const float* h = g_hid + (size_t)row * DD;
    float s = 0.0f;
    for (int d = tid; d < DD; d += 128) s = fmaf(h[d], Wi2[d], s);
    #pragma unroll
    for (int o = 16; o > 0; o >>= 1) s += __shfl_down_sync(0xffffffffu, s, o);
    __shared__ float red[4];
    if ((tid & 31) == 0) red[tid >> 5] = s;
    __syncthreads();
    if (tid == 0)
        g_implog[row] = red[0] + red[1] + red[2] + red[3] + bi2[0];
}

__global__ void imp_kernel(float* __restrict__ out_imp)
{
    const int b = blockIdx.x;
    if (threadIdx.x != 0) return;
    float l[7], mx = -1e30f;
    #pragma unroll
    for (int n = 0; n < 7; n++) { l[n] = g_implog[b * 7 + n]; mx = fmaxf(mx, l[n]); }
    float s = 0.0f;
    #pragma unroll
    for (int n = 0; n < 7; n++) { l[n] = expf(l[n] - mx); s += l[n]; }
    float imp[7];
    #pragma unroll
    for (int n = 0; n < 7; n++) imp[n] = l[n] / s;

    const float cap[7] = {1.f,1.f,1.f,0.26f,1.f,1.f,0.24f};
    const float fr [7] = {1.f,1.f,1.f,0.f,  1.f,1.f,0.f };
    float capped[7], sc = 0.0f, fm = 0.0f;
    #pragma unroll
    for (int n = 0; n < 7; n++) {
        capped[n] = fminf(imp[n], cap[n]);
        sc += capped[n];
        fm += imp[n] * fr[n];
    }
    float residual = fmaxf(1.0f - sc, 0.0f);
    float redis[7], sr = 0.0f;
    #pragma unroll
    for (int n = 0; n < 7; n++) {
        float fs = (fm > 1e-6f) ? imp[n] * fr[n] / fmaxf(fm, 1e-6f) : fr[n] / 5.0f;
        redis[n] = capped[n] + fs * residual;
        sr += redis[n];
    }
    #pragma unroll
    for (int n = 0; n < 7; n++)
        out_imp[b * 7 + n] = redis[n] / fmaxf(sr, 1e-6f);
}

__global__ __launch_bounds__(256)
void fused_kernel(const float* __restrict__ out_imp,
                  const float* __restrict__ upd,
                  float* __restrict__ out_fused)
{
    const int b = blockIdx.x;
    const int tid = threadIdx.x;
    __shared__ float w[7];
    if (tid < 7) w[tid] = out_imp[b * 7 + tid];
    __syncthreads();
    const float* u = upd + (size_t)b * NN * DD;
    for (int d = tid; d < DD; d += 256) {
        float acc = 0.0f;
        #pragma unroll
        for (int n = 0; n < 7; n++) acc = fmaf(w[n], u[n * DD + d], acc);
        out_fused[(size_t)b * DD + d] = acc;
    }
}

__global__ __launch_bounds__(256)
void physalign_kernel(const float* __restrict__ upd,
                      const float* __restrict__ fused)
{
    const int b = blockIdx.x;
    const int tid = threadIdx.x;
    const int lane = tid & 31, wid = tid >> 5;
    __shared__ float dots[57];
    const float* u = upd   + (size_t)b * NN * DD;
    const float* f = fused + (size_t)b * DD;

    for (int t = wid; t < 57; t += 8) {
        const float *x, *y;
        if (t < 49)      { x = u + (t / 7) * DD; y = u + (t % 7) * DD; }
        else if (t < 56) { x = u + (t - 49) * DD; y = f; }
        else             { x = f; y = f; }
        float s = 0.0f;
        for (int d = lane; d < DD; d += 32) s = fmaf(x[d], y[d], s);
        #pragma unroll
        for (int o = 16; o > 0; o >>= 1) s += __shfl_down_sync(0xffffffffu, s, o);
        if (lane == 0) dots[t] = s;
    }
    __syncthreads();

    if (tid == 0) {
        float norms[7];
        #pragma unroll
        for (int n = 0; n < 7; n++) norms[n] = sqrtf(dots[n * 7 + n]);
        float edge = 0.0f, non = 0.0f;
        #pragma unroll
        for (int n = 0; n < 7; n++) {
            #pragma unroll
            for (int m = 0; m < 7; m++) {
                float cs = dots[n * 7 + m] / fmaxf(norms[n] * norms[m], 1e-8f);
                float a = c_adj[n * 7 + m];
                edge += (1.0f - cs) * a;
                float nonmask = (1.0f - a) * ((n == m) ? 0.0f : 1.0f);
                non += fmaxf(cs - 0.35f, 0.0f) * nonmask;
            }
        }
        g_phys_part[b] = edge / 41.0f + 0.5f * non / 8.0f;

        float fn = sqrtf(dots[56]);
        float al = 0.0f;
        #pragma unroll
        for (int n = 0; n < 7; n++) {
            float cs = dots[49 + n] / (fmaxf(norms[n], 1e-12f) * fmaxf(fn, 1e-12f));
            al += 1.0f - cs;
        }
        g_align_part[b] = al;
    }
}

__global__ __launch_bounds__(256)
void final_reduce_kernel(float* __restrict__ out)
{
    const int tid = threadIdx.x;
    float p = 0.0f, a = 0.0f;
    for (int b = tid; b < BB; b += 256) { p += g_phys_part[b]; a += g_align_part[b]; }
    __shared__ float sp[256], sa[256];
    sp[tid] = p; sa[tid] = a;
    __syncthreads();
    for (int s = 128; s > 0; s >>= 1) {
        if (tid < s) { sp[tid] += sp[tid + s]; sa[tid] += sa[tid + s]; }
        __syncthreads();
    }
    if (tid == 0) {
        out[OFF_PHYS]  = sp[0];
        out[OFF_ALIGN] = sa[0] / (float)(BB * NN);
    }
}

// ---------------------------------------------------------------------------
extern "C" void kernel_launch(void* const* d_in, const int* in_sizes, int n_in,
                              void* d_out, int out_size)
{
    const float* nodes = (const float*)d_in[0];
    const float* Wq    = (const float*)d_in[1];
    const float* bq    = (const float*)d_in[2];
    const float* Wk    = (const float*)d_in[3];
    const float* bk    = (const float*)d_in[4];
    const float* Wv    = (const float*)d_in[5];
    const float* bv    = (const float*)d_in[6];
    const float* We1   = (const float*)d_in[7];
    const float* be1   = (const float*)d_in[8];
    const float* We2   = (const float*)d_in[9];
    const float* be2   = (const float*)d_in[10];
    const float* Wu1   = (const float*)d_in[11];
    const float* bu1   = (const float*)d_in[12];
    const float* Wu2   = (const float*)d_in[13];
    const float* bu2   = (const float*)d_in[14];
    const float* Wi1   = (const float*)d_in[15];
    const float* bi1   = (const float*)d_in[16];
    const float* Wi2   = (const float*)d_in[17];
    const float* bi2   = (const float*)d_in[18];

    float* out       = (float*)d_out;
    float* out_fused = out + OFF_FUSED;
    float* out_upd   = out + OFF_UPD;
    float* out_imp   = out + OFF_IMP;
    float* out_attn  = out + OFF_ATTN;

    float* qkv = nullptr; cudaGetSymbolAddress((void**)&qkv, g_qkv);
    float* cc  = nullptr; cudaGetSymbolAddress((void**)&cc,  g_cc);
    float* hid = nullptr; cudaGetSymbolAddress((void**)&hid, g_hid);
    float* bpk = nullptr; cudaGetSymbolAddress((void**)&bpk, g_bpack);

    uint32_t *ndH=nullptr,*ndL=nullptr,*ctH=nullptr,*ctL=nullptr,*hpH=nullptr,*hpL=nullptr;
    cudaGetSymbolAddress((void**)&ndH, g_nodes_h);
    cudaGetSymbolAddress((void**)&ndL, g_nodes_l);
    cudaGetSymbolAddress((void**)&ctH, g_cat_h);
    cudaGetSymbolAddress((void**)&ctL, g_cat_l);
    cudaGetSymbolAddress((void**)&hpH, g_hidp_h);
    cudaGetSymbolAddress((void**)&hpL, g_hidp_l);

    uint32_t *WprH=nullptr,*WprL=nullptr,*WcH=nullptr,*WcL=nullptr;
    uint32_t *Wu1H=nullptr,*Wu1L=nullptr,*Wu2H=nullptr,*Wu2L=nullptr,*Wi1H=nullptr,*Wi1L=nullptr;
    cudaGetSymbolAddress((void**)&WprH, g_Wproj_h);
    cudaGetSymbolAddress((void**)&WprL, g_Wproj_l);
    cudaGetSymbolAddress((void**)&WcH,  g_Wc_h);
    cudaGetSymbolAddress((void**)&WcL,  g_Wc_l);
    cudaGetSymbolAddress((void**)&Wu1H, g_Wu1_h);
    cudaGetSymbolAddress((void**)&Wu1L, g_Wu1_l);
    cudaGetSymbolAddress((void**)&Wu2H, g_Wu2_h);
    cudaGetSymbolAddress((void**)&Wu2L, g_Wu2_l);
    cudaGetSymbolAddress((void**)&Wi1H, g_Wi1_h);
    cudaGetSymbolAddress((void**)&Wi1L, g_Wi1_l);

    cudaFuncSetAttribute(gemm_bf16x2_kernel,
                         cudaFuncAttributeMaxDynamicSharedMemorySize,
                         SMEM_GEMM_BYTES);

    dim3 blk(256);
    const size_t shm = SMEM_GEMM_BYTES;

    // ---- pre-split activations / pack weights ----
    {
        size_t n;
        n = (size_t)MM * DD / 2;
        split_nodes_kernel<<<(unsigned)((n + 255) / 256), blk>>>(nodes);
        n = (size_t)(DD / 2) * NP;
        pack_proj_w_kernel<<<(unsigned)((n + 255) / 256), blk>>>(Wq, Wk, Wv, We1);
        pack_b_kernel<<<(NP + 255) / 256, blk>>>(bq, bk, bv);
        n = (size_t)(DD / 2) * DD;
        pack_w_gen_kernel<<<(unsigned)((n + 255) / 256), blk>>>(
            We1 + (size_t)2 * DD * DD, DD, DD, WcH, WcL);
        pack_w_gen_kernel<<<(unsigned)((n + 255) / 256), blk>>>(Wu2, DD, DD, Wu2H, Wu2L);
        n = (size_t)DD * DD;
        pack_w_gen_kernel<<<(unsigned)((n + 255) / 256), blk>>>(Wu1, 2 * DD, DD, Wu1H, Wu1L);
        pack_w_gen_kernel<<<(unsigned)((n + 255) / 256), blk>>>(Wi1, 2 * DD, DD, Wi1H, Wi1L);
    }

    // ---- merged projections: [7168,1024] x [1024,5120] -> qkv ----
    dim3 grid_proj(NP / 128, MM / 128);     // 40 x 56
    gemm_bf16x2_kernel<<<grid_proj, blk, shm>>>(MM, NP, DD,
        ndH, ndL, DD / 2, WprH, WprL, bpk, nullptr, qkv, nullptr, nullptr, 0);

    // ---- cc projection (last node rows) ----
    dim3 grid_cc(DD / 128, BB / 128);       // 8 x 8
    gemm_bf16x2_kernel<<<grid_cc, blk, shm>>>(BB, DD, DD,
        ndH + (size_t)(NN - 1) * DD / 2, ndL + (size_t)(NN - 1) * DD / 2, NN * DD / 2,
        WcH, WcL, nullptr, nullptr, cc, nullptr, nullptr, 0);

    // ---- attention ----
    attn_kernel<<<BB, blk>>>(be1, We2, be2, out_attn);

    // ---- update MLP ----
    dim3 grid_big(DD / 128, MM / 128);      // 8 x 56
    {
        size_t n = (size_t)MM * DD;
        concat_nm_kernel<<<(unsigned)((n + 255) / 256), blk>>>(nodes);
    }
    gemm_bf16x2_kernel<<<grid_big, blk, shm>>>(MM, DD, 2 * DD,
        ctH, ctL, DD, Wu1H, Wu1L, bu1, nullptr, nullptr, hpH, hpL, 1);
    gemm_bf16x2_kernel<<<grid_big, blk, shm>>>(MM, DD, DD,
        hpH, hpL, DD / 2, Wu2H, Wu2L, bu2, nodes, out_upd, nullptr, nullptr, 0);

    // ---- importance MLP ----
    {
        size_t n = (size_t)MM * DD;
        concat_ug_kernel<<<(unsigned)((n + 255) / 256), blk>>>(out_upd);
    }
    gemm_bf16x2_kernel<<<grid_big, blk, shm>>>(MM, DD, 2 * DD,
        ctH, ctL, DD, Wi1H, Wi1L, bi1, nullptr, hid, nullptr, nullptr, 1);
    gemv_imp_kernel<<<MM, 128>>>(Wi2, bi2);
    imp_kernel<<<BB, 32>>>(out_imp);

    // ---- fused output + losses ----
    fused_kernel<<<BB, blk>>>(out_imp, out_upd, out_fused);
    physalign_kernel<<<BB, blk>>>(out_upd, out_fused);
    final_reduce_kernel<<<1, blk>>>(out);
}